// round 14
// baseline (speedup 1.0000x reference)
#include <cuda_runtime.h>
#include <cuda_bf16.h>
#include <cstdint>

#define BB    16
#define HWSZ  4096
#define DIMC  256
#define NQKV  192
#define NHD   8
#define CRN   64
#define SCALEF 0.17677669529663687f
#define PLANE 364
#define RSTR  36

// int8 quantization constants (SA exact power of two)
#define SA_F     0.00048828125f          // 2^-11
#define SW_F     9.1552734e-6f           // 0.15/16384
#define S2_F     (SA_F * SW_F)

typedef unsigned long long ull;
typedef unsigned int u32;

// ---------------- device scratch (allocation-free rule) ----------------
__device__ float g_qkv[BB * NQKV * HWSZ];               // (B,192,4096) fp32
__device__ char  g_x1[BB * HWSZ * DIMC];                // x int8 level-1, (B,4096,256)
__device__ char  g_x2[BB * HWSZ * DIMC];                // x int8 level-2
__device__ __nv_bfloat16 g_yt_hi[BB * NHD * HWSZ * 8];  // (B,8,4096,8) head-major
__device__ __nv_bfloat16 g_yt_lo[BB * NHD * HWSZ * 8];
__device__ char  g_wq1[NQKV * DIMC];
__device__ char  g_wq2[NQKV * DIMC];
__device__ __nv_bfloat16 g_wp_hi[DIMC * CRN];
__device__ __nv_bfloat16 g_wp_lo[DIMC * CRN];

// ---------------- PTX helpers ----------------
__device__ __forceinline__ ull fma2(ull a, ull b, ull c) {
    ull d; asm("fma.rn.f32x2 %0, %1, %2, %3;" : "=l"(d) : "l"(a), "l"(b), "l"(c)); return d;
}
__device__ __forceinline__ ull add2(ull a, ull b) {
    ull d; asm("add.rn.f32x2 %0, %1, %2;" : "=l"(d) : "l"(a), "l"(b)); return d;
}
__device__ __forceinline__ ull mul2(ull a, ull b) {
    ull d; asm("mul.rn.f32x2 %0, %1, %2;" : "=l"(d) : "l"(a), "l"(b)); return d;
}
__device__ __forceinline__ ull pack2(float lo, float hi) {
    ull d; asm("mov.b64 %0, {%1, %2};" : "=l"(d)
        : "r"(__float_as_uint(lo)), "r"(__float_as_uint(hi))); return d;
}
__device__ __forceinline__ float lo32(ull v) { return __uint_as_float((unsigned)(v & 0xffffffffu)); }
__device__ __forceinline__ float hi32(ull v) { return __uint_as_float((unsigned)(v >> 32)); }

__device__ __forceinline__ void cp16(void* smem, const void* g) {
    unsigned s = (unsigned)__cvta_generic_to_shared(smem);
    asm volatile("cp.async.cg.shared.global [%0], [%1], 16;" :: "r"(s), "l"(g));
}
__device__ __forceinline__ void cp_commit() { asm volatile("cp.async.commit_group;"); }
__device__ __forceinline__ void cp_wait1()  { asm volatile("cp.async.wait_group 1;"); }
__device__ __forceinline__ void cp_wait0()  { asm volatile("cp.async.wait_group 0;"); }

__device__ __forceinline__ u32 smem_u32(const void* p) {
    return (u32)__cvta_generic_to_shared(p);
}
__device__ __forceinline__ void ldsm4(u32* r, u32 addr) {
    asm volatile("ldmatrix.sync.aligned.m8n8.x4.shared.b16 {%0,%1,%2,%3}, [%4];"
        : "=r"(r[0]), "=r"(r[1]), "=r"(r[2]), "=r"(r[3]) : "r"(addr));
}
__device__ __forceinline__ void mma16816(float* c, const u32* a, const u32* b) {
    asm volatile(
        "mma.sync.aligned.m16n8k16.row.col.f32.bf16.bf16.f32 "
        "{%0,%1,%2,%3}, {%4,%5,%6,%7}, {%8,%9}, {%0,%1,%2,%3};"
        : "+f"(c[0]), "+f"(c[1]), "+f"(c[2]), "+f"(c[3])
        : "r"(a[0]), "r"(a[1]), "r"(a[2]), "r"(a[3]), "r"(b[0]), "r"(b[1]));
}
__device__ __forceinline__ void mma16832s8(int* c, const u32* a, const u32* b) {
    asm volatile(
        "mma.sync.aligned.m16n8k32.row.col.s32.s8.s8.s32 "
        "{%0,%1,%2,%3}, {%4,%5,%6,%7}, {%8,%9}, {%0,%1,%2,%3};"
        : "+r"(c[0]), "+r"(c[1]), "+r"(c[2]), "+r"(c[3])
        : "r"(a[0]), "r"(a[1]), "r"(a[2]), "r"(a[3]), "r"(b[0]), "r"(b[1]));
}
__device__ __forceinline__ int clamp127(int v) {
    return max(-127, min(127, v));
}

// ---------------- weight conversion: qkv -> int8 2-level; proj -> bf16 split ----------------
__global__ void convert_w_kernel(const float* __restrict__ qkv_w,
                                 const float* __restrict__ proj_w) {
    int i = blockIdx.x * 256 + threadIdx.x;
    if (i < NQKV * DIMC) {
        float v = qkv_w[i];
        int w1i = clamp127(__float2int_rn(v * (1.f / (128.f * SW_F))));
        float r = v - (float)w1i * (128.f * SW_F);
        int w2i = clamp127(__float2int_rn(r * (1.f / SW_F)));
        g_wq1[i] = (char)w1i;
        g_wq2[i] = (char)w2i;
    }
    if (i < DIMC * CRN) {
        float v = proj_w[i];
        __nv_bfloat16 h = __float2bfloat16(v);
        g_wp_hi[i] = h;
        g_wp_lo[i] = __float2bfloat16(v - __bfloat162float(h));
    }
}

// ---------------- transpose + int8 quant: x [b][256][4096] -> xt [b][4096][256] s8 x2 ----------------
__global__ void tquant_kernel(const float* __restrict__ src,
                              char* __restrict__ d1,
                              char* __restrict__ d2) {
    __shared__ float t[32][33];
    const int b  = blockIdx.z;
    const int m0 = blockIdx.x * 32;
    const int c0 = blockIdx.y * 32;
    const int tx = threadIdx.x, ty = threadIdx.y;   // 32 x 8
    const float* s = src + ((long)b * DIMC + c0) * HWSZ + m0;
#pragma unroll
    for (int j = 0; j < 32; j += 8)
        t[ty + j][tx] = s[(long)(ty + j) * HWSZ + tx];
    __syncthreads();
    char* p1 = d1 + ((long)b * HWSZ + m0) * DIMC + c0;
    char* p2 = d2 + ((long)b * HWSZ + m0) * DIMC + c0;
#pragma unroll
    for (int j = 0; j < 32; j += 8) {
        float v = t[tx][ty + j];
        int a1 = clamp127(__float2int_rn(v * 16.f));        // 1/(128*SA) = 16
        float r = v - (float)a1 * 0.0625f;                  // 128*SA = 1/16
        int a2 = clamp127(__float2int_rn(r * 2048.f));      // 1/SA = 2048
        p1[(long)(ty + j) * DIMC + tx] = (char)a1;
        p2[(long)(ty + j) * DIMC + tx] = (char)a2;
    }
}

// ---------------- int8 2-level mma GEMM (qkv) ----------------
// out[b][n][m] = S2*(16384*acc1 + 128*accX) + bias[n]
// CTA 128m x 64n, 512 threads (16 warps: 4m x 4n), warp tile 32m x 16n, BK=64.
#define STG8  30720
#define ROWB8 80    // 64B data + 16B pad

__global__ __launch_bounds__(512) void gemm_s8_kernel(
    const char* __restrict__ a1g, const char* __restrict__ a2g,
    const char* __restrict__ w1g, const char* __restrict__ w2g,
    const float* __restrict__ bias, float* __restrict__ out, int N)
{
    extern __shared__ char sm[];
    const int tid  = threadIdx.x;
    const int lane = tid & 31;
    const int warp = tid >> 5;
    const int wm   = warp & 3;    // 0..3
    const int wn   = warp >> 2;   // 0..3
    const int b    = blockIdx.z;
    const int m0   = blockIdx.x * 128;
    const int n0   = blockIdx.y * 64;

    const int a_row  = lane & 15;
    const int a_colB = (lane >> 4) * 16;
    const int b_row  = (lane & 7) + ((lane >> 4) & 1) * 8;
    const int b_colB = ((lane >> 3) & 1) * 16;

    const int aoff = (wm * 32 + a_row) * ROWB8 + a_colB;
    const int boff = (wn * 16 + b_row) * ROWB8 + b_colB;

    int acc1[2][2][4], accX[2][2][4];
#pragma unroll
    for (int mt = 0; mt < 2; mt++)
#pragma unroll
        for (int ni = 0; ni < 2; ni++)
#pragma unroll
            for (int r = 0; r < 4; r++) { acc1[mt][ni][r] = 0; accX[mt][ni][r] = 0; }

    auto load_stage = [&](int s, int k0) {
        char* A1 = sm + s * STG8;
        char* A2 = A1 + 10240;
        char* B1 = A1 + 20480;
        char* B2 = A1 + 25600;
        if (tid < 512) {
            int r = tid >> 2, j = tid & 3;
            long go = ((long)b * HWSZ + m0 + r) * DIMC + k0 + j * 16;
            cp16(A1 + r * ROWB8 + j * 16, a1g + go);
            cp16(A2 + r * ROWB8 + j * 16, a2g + go);
        }
        if (tid < 256) {
            int r = tid >> 2, j = tid & 3;
            long go = (long)(n0 + r) * DIMC + k0 + j * 16;
            cp16(B1 + r * ROWB8 + j * 16, w1g + go);
            cp16(B2 + r * ROWB8 + j * 16, w2g + go);
        }
        cp_commit();
    };

    load_stage(0, 0);

    const int KT = DIMC / 64;   // 4
    for (int kt = 0; kt < KT; kt++) {
        const int cur = kt & 1;
        const bool more = (kt + 1 < KT);
        if (more) load_stage(cur ^ 1, (kt + 1) * 64);
        if (more) cp_wait1(); else cp_wait0();
        __syncthreads();

        const char* sb = sm + cur * STG8;
        const u32 A1 = smem_u32(sb) + aoff;
        const u32 A2 = A1 + 10240;
        const u32 B1 = smem_u32(sb) + 20480 + boff;
        const u32 B2 = B1 + 5120;

#pragma unroll
        for (int kk = 0; kk < 2; kk++) {
            u32 a1f[2][4], a2f[2][4], b1f[4], b2f[4];
#pragma unroll
            for (int mt = 0; mt < 2; mt++) {
                ldsm4(a1f[mt], A1 + mt * 16 * ROWB8 + kk * 32);
                ldsm4(a2f[mt], A2 + mt * 16 * ROWB8 + kk * 32);
            }
            ldsm4(b1f, B1 + kk * 32);
            ldsm4(b2f, B2 + kk * 32);
#pragma unroll
            for (int mt = 0; mt < 2; mt++)
#pragma unroll
                for (int ni = 0; ni < 2; ni++) {
                    const int h = ni * 2;
                    mma16832s8(acc1[mt][ni], a1f[mt], &b1f[h]);
                    mma16832s8(accX[mt][ni], a1f[mt], &b2f[h]);
                    mma16832s8(accX[mt][ni], a2f[mt], &b1f[h]);
                }
        }
        __syncthreads();
    }

    // epilogue: dequant, stage via smem, coalesced n-major writes
    float* Cs = (float*)sm;
#pragma unroll
    for (int mt = 0; mt < 2; mt++)
#pragma unroll
        for (int ni = 0; ni < 2; ni++) {
            int mm = wm * 32 + mt * 16 + (lane >> 2);
            int nn = wn * 16 + ni * 8 + (lane & 3) * 2;
            float v0 = S2_F * (16384.f * (float)acc1[mt][ni][0] + 128.f * (float)accX[mt][ni][0]);
            float v1 = S2_F * (16384.f * (float)acc1[mt][ni][1] + 128.f * (float)accX[mt][ni][1]);
            float v2 = S2_F * (16384.f * (float)acc1[mt][ni][2] + 128.f * (float)accX[mt][ni][2]);
            float v3 = S2_F * (16384.f * (float)acc1[mt][ni][3] + 128.f * (float)accX[mt][ni][3]);
            *(float2*)&Cs[mm * 66 + nn]       = make_float2(v0, v1);
            *(float2*)&Cs[(mm + 8) * 66 + nn] = make_float2(v2, v3);
        }
    __syncthreads();
    for (int u = tid; u < 64 * 128; u += 512) {
        int n = u >> 7, m = u & 127;
        out[((long)b * N + n0 + n) * HWSZ + m0 + m] = Cs[m * 66 + n] + __ldg(&bias[n0 + n]);
    }
}

// ---------------- bf16-split mma.sync GEMM (proj) ----------------
#define STG   30720
#define AROWB 80

__global__ __launch_bounds__(256) void gemm_mma_kernel(
    const __nv_bfloat16* __restrict__ aT_hi,
    const __nv_bfloat16* __restrict__ aT_lo,
    const __nv_bfloat16* __restrict__ w_hi,
    const __nv_bfloat16* __restrict__ w_lo,
    const float* __restrict__ bias,
    float* __restrict__ out, int N, int K,
    long aBatch, long aRow, long aK, long aChunk)
{
    extern __shared__ char sm[];
    const int tid  = threadIdx.x;
    const int lane = tid & 31;
    const int warp = tid >> 5;
    const int wm   = warp & 3;
    const int wn   = warp >> 2;
    const int b    = blockIdx.z;
    const int m0   = blockIdx.x * 128;
    const int n0   = blockIdx.y * 64;

    const long abase0 = (long)b * aBatch + (long)m0 * aRow;

    const int a_row  = lane & 15;
    const int a_colB = (lane >> 4) * 16;
    const int b_row  = (lane & 7) + ((lane >> 4) & 1) * 8;
    const int b_colB = ((lane >> 3) & 1) * 16;

    const int aoff = (wm * 32 + a_row) * AROWB + a_colB;
    const int boff = (wn * 32 + b_row) * AROWB + b_colB;

    float acc[2][4][4];
#pragma unroll
    for (int mt = 0; mt < 2; mt++)
#pragma unroll
        for (int ni = 0; ni < 4; ni++)
#pragma unroll
            for (int r = 0; r < 4; r++) acc[mt][ni][r] = 0.f;

    const int KT = K >> 5;

    auto load_stage = [&](int s, int k0) {
        char* Ah = sm + s * STG;
        char* Al = Ah + 10240;
        char* Bh = Ah + 20480;
        char* Bl = Ah + 25600;
        const long abase = abase0 + (long)k0 * aK;
        for (int u = tid; u < 512; u += 256) {
            int r = u >> 2, j = u & 3;
            long go = abase + r * aRow + j * aChunk;
            cp16(Ah + r * AROWB + j * 16, aT_hi + go);
            cp16(Al + r * AROWB + j * 16, aT_lo + go);
        }
        for (int u = tid; u < 256; u += 256) {
            int r = u >> 2, j = u & 3;
            long go = (long)(n0 + r) * K + k0 + j * 8;
            cp16(Bh + r * AROWB + j * 16, w_hi + go);
            cp16(Bl + r * AROWB + j * 16, w_lo + go);
        }
        cp_commit();
    };

    load_stage(0, 0);

    for (int kt = 0; kt < KT; kt++) {
        const int cur = kt & 1;
        const bool more = (kt + 1 < KT);
        if (more) load_stage(cur ^ 1, (kt + 1) * 32);
        if (more) cp_wait1(); else cp_wait0();
        __syncthreads();

        const char* sb = sm + cur * STG;
        const u32 aH = smem_u32(sb) + aoff;
        const u32 aL = aH + 10240;
        const u32 bH = smem_u32(sb) + 20480 + boff;
        const u32 bL = bH + 5120;

#pragma unroll
        for (int kk = 0; kk < 2; kk++) {
            u32 ah[2][4], al[2][4], bh[2][4], bl[2][4];
#pragma unroll
            for (int mt = 0; mt < 2; mt++) {
                ldsm4(ah[mt], aH + mt * 16 * AROWB + kk * 32);
                ldsm4(al[mt], aL + mt * 16 * AROWB + kk * 32);
            }
#pragma unroll
            for (int bt = 0; bt < 2; bt++) {
                ldsm4(bh[bt], bH + bt * 16 * AROWB + kk * 32);
                ldsm4(bl[bt], bL + bt * 16 * AROWB + kk * 32);
            }
#pragma unroll
            for (int mt = 0; mt < 2; mt++)
#pragma unroll
                for (int ni = 0; ni < 4; ni++) {
                    const int bt = ni >> 1, h = (ni & 1) * 2;
                    mma16816(acc[mt][ni], ah[mt], &bh[bt][h]);
                    mma16816(acc[mt][ni], ah[mt], &bl[bt][h]);
                    mma16816(acc[mt][ni], al[mt], &bh[bt][h]);
                }
        }
        __syncthreads();
    }

    float* Cs = (float*)sm;
#pragma unroll
    for (int mt = 0; mt < 2; mt++)
#pragma unroll
        for (int ni = 0; ni < 4; ni++) {
            int mm = wm * 32 + mt * 16 + (lane >> 2);
            int nn = wn * 32 + ni * 8 + (lane & 3) * 2;
            *(float2*)&Cs[mm * 66 + nn]       = make_float2(acc[mt][ni][0], acc[mt][ni][1]);
            *(float2*)&Cs[(mm + 8) * 66 + nn] = make_float2(acc[mt][ni][2], acc[mt][ni][3]);
        }
    __syncthreads();
    for (int u = tid; u < 64 * 128; u += 256) {
        int n = u >> 7, m = u & 127;
        out[((long)b * N + n0 + n) * HWSZ + m0 + m] = Cs[m * 66 + n] + __ldg(&bias[n0 + n]);
    }
}

// ---------------- fused slide attention (R12 version, unchanged) ----------------
__global__ __launch_bounds__(128, 3) void attn_kernel(
    const float* __restrict__ qkv,
    const float* __restrict__ w1,
    const float* __restrict__ dcb,
    const float* __restrict__ dc1b,
    const float* __restrict__ rpb,
    __nv_bfloat16* __restrict__ yh,
    __nv_bfloat16* __restrict__ yl)
{
    const int b   = blockIdx.z;
    const int hd  = blockIdx.y;
    const int rt  = blockIdx.x >> 1;
    const int ct  = blockIdx.x & 1;
    const int h0  = rt * 8;
    const int gw0 = ct * 32;

    __shared__ float sk[8 * PLANE];
    __shared__ float sv[8 * PLANE];
    __shared__ ull   sw2[8][81];
    __shared__ ull   sbk2[8][9];
    __shared__ ull   sbv2[8][9];
    __shared__ __nv_bfloat16 syh[256 * 8];
    __shared__ __nv_bfloat16 syl[256 * 8];

    const int tid  = threadIdx.x;
    const int lane = tid & 31;
    const int warp = tid >> 5;
    const int c    = lane & 7;
    const int g    = lane >> 3;

    const float* base = qkv + ((long)b * NQKV + hd * 24) * HWSZ;

    for (int i = tid; i < 648; i += 128) {
        int cc = i / 81, idx = i - cc * 81;
        int t = idx / 9, ii = idx - t * 9;
        float w = w1[cc * 81 + idx] + (t == ii ? 1.f : 0.f);
        sw2[cc][idx] = pack2(w, w);
    }
    for (int i = tid; i < 72; i += 128) {
        int cc = i / 9, t = i - cc * 9;
        float bb = dcb[i] + dc1b[i];
        sbv2[cc][t] = pack2(bb, bb);
        float bk = bb + rpb[hd * 9 + t];
        sbk2[cc][t] = pack2(bk, bk);
    }
    for (int i = tid; i < 8 * 340; i += 128) {
        int cc = i / 340, rem = i - cc * 340;
        int yy = rem / 34, xx = rem - yy * 34;
        int gh = h0 + yy - 1;
        int gx = gw0 + xx - 1;
        float kk = 0.f, vv = 0.f;
        if (gh >= 0 && gh < 64 && gx >= 0 && gx < 64) {
            long off = (long)(8 + cc) * HWSZ + gh * 64 + gx;
            kk = base[off];
            vv = base[off + 8 * HWSZ];
        }
        sk[cc * PLANE + yy * RSTR + xx] = kk;
        sv[cc * PLANE + yy * RSTR + xx] = vv;
    }
    __syncthreads();

    const ull* wrow = sw2[c];

#pragma unroll 1
    for (int step = 0; step < 4; step++) {
        const int task = step * 4 + warp;
        const int row  = task >> 1;
        const int half = task & 1;
        const int w0   = half * 16 + g * 4;
        const int hw   = (h0 + row) * 64 + gw0 + w0;

        float4 qv = *(const float4*)&base[(long)c * HWSZ + hw];
        ull q0 = pack2(qv.x * SCALEF, qv.y * SCALEF);
        ull q1 = pack2(qv.z * SCALEF, qv.w * SCALEF);

        ull nn[3][5];

        {
            const float* p = &sk[c * PLANE + row * RSTR + w0];
#pragma unroll
            for (int ty = 0; ty < 3; ty++) {
                float4 a  = *(const float4*)(p + ty * RSTR);
                float2 a2 = *(const float2*)(p + ty * RSTR + 4);
                nn[ty][0] = pack2(a.x, a.y);
                nn[ty][1] = pack2(a.y, a.z);
                nn[ty][2] = pack2(a.z, a.w);
                nn[ty][3] = pack2(a.w, a2.x);
                nn[ty][4] = pack2(a2.x, a2.y);
            }
        }

        ull lg0[9], lg1[9];
#pragma unroll
        for (int t = 0; t < 9; t++) {
            ull kv0 = sbk2[c][t];
            ull kv1 = kv0;
#pragma unroll
            for (int i = 0; i < 9; i++) {
                const int iy = i / 3, ix = i - iy * 3;
                ull wp = wrow[t * 9 + i];
                kv0 = fma2(wp, nn[iy][ix],     kv0);
                kv1 = fma2(wp, nn[iy][ix + 2], kv1);
            }
            lg0[t] = mul2(q0, kv0);
            lg1[t] = mul2(q1, kv1);
        }

#pragma unroll
        for (int off = 4; off >= 1; off >>= 1)
#pragma unroll
            for (int t = 0; t < 9; t++) {
                lg0[t] = add2(lg0[t], __shfl_xor_sync(0xffffffffu, lg0[t], off));
                lg1[t] = add2(lg1[t], __shfl_xor_sync(0xffffffffu, lg1[t], off));
            }

        ull s0 = 0ULL, s1 = 0ULL;
#pragma unroll
        for (int t = 0; t < 9; t++) {
            lg0[t] = pack2(__expf(lo32(lg0[t])), __expf(hi32(lg0[t])));
            lg1[t] = pack2(__expf(lo32(lg1[t])), __expf(hi32(lg1[t])));
            s0 = add2(s0, lg0[t]);
            s1 = add2(s1, lg1[t]);
        }
        ull inv0 = pack2(__fdividef(1.f, lo32(s0)), __fdividef(1.f, hi32(s0)));
        ull inv1 = pack2(__fdividef(1.f, lo32(s1)), __fdividef(1.f, hi32(s1)));

        {
            const float* p = &sv[c * PLANE + row * RSTR + w0];
#pragma unroll
            for (int ty = 0; ty < 3; ty++) {
                float4 a  = *(const float4*)(p + ty * RSTR);
                float2 a2 = *(const float2*)(p + ty * RSTR + 4);
                nn[ty][0] = pack2(a.x, a.y);
                nn[ty][1] = pack2(a.y, a.z);
                nn[ty][2] = pack2(a.z, a.w);
                nn[ty][3] = pack2(a.w, a2.x);
                nn[ty][4] = pack2(a2.x, a2.y);
            }
        }
        ull o0 = 0ULL, o1 = 0ULL;
#pragma unroll
        for (int t = 0; t < 9; t++) {
            ull vv0 = sbv2[c][t];
            ull vv1 = vv0;
#pragma unroll
            for (int i = 0; i < 9; i++) {
                const int iy = i / 3, ix = i - iy * 3;
                ull wp = wrow[t * 9 + i];
                vv0 = fma2(wp, nn[iy][ix],     vv0);
                vv1 = fma2(wp, nn[iy][ix + 2], vv1);
            }
            o0 = fma2(lg0[t], vv0, o0);
            o1 = fma2(lg1[t], vv1, o1);
        }
        o0 = mul2(o0, inv0);
        o1 = mul2(o1, inv1);

        const int lpos = row * 32 + w0;
        float o[4] = { lo32(o0), hi32(o0), lo32(o1), hi32(o1) };
#pragma unroll
        for (int p = 0; p < 4; p++) {
            __nv_bfloat16 hb = __float2bfloat16(o[p]);
            syh[(lpos + p) * 8 + c] = hb;
            syl[(lpos + p) * 8 + c] = __float2bfloat16(o[p] - __bfloat162float(hb));
        }
    }
    __syncthreads();

    const long ybase0 = ((long)b * NHD + hd) * HWSZ * 8;
    const uint4* sh4 = (const uint4*)syh;
    const uint4* sl4 = (const uint4*)syl;
    for (int i = tid; i < 256; i += 128) {
        int row = i >> 5, j = i & 31;
        long gdst = ybase0 + ((long)(h0 + row) * 64 + gw0) * 8 + j * 8;
        *(uint4*)&yh[gdst] = sh4[i];
        *(uint4*)&yl[gdst] = sl4[i];
    }
}

// ---------------- launch ----------------
extern "C" void kernel_launch(void* const* d_in, const int* in_sizes, int n_in,
                              void* d_out, int out_size) {
    const float* x      = (const float*)d_in[0];
    const float* qkv_w  = (const float*)d_in[5];
    const float* qkv_b  = (const float*)d_in[6];
    const float* dcb    = (const float*)d_in[7];
    const float* w1     = (const float*)d_in[8];
    const float* dc1b   = (const float*)d_in[9];
    const float* rpb    = (const float*)d_in[10];
    const float* proj_w = (const float*)d_in[11];
    const float* proj_b = (const float*)d_in[12];
    float* out = (float*)d_out;

    float* qkv = nullptr;
    cudaGetSymbolAddress((void**)&qkv, g_qkv);
    char *x1, *x2, *wq1, *wq2;
    cudaGetSymbolAddress((void**)&x1, g_x1);
    cudaGetSymbolAddress((void**)&x2, g_x2);
    cudaGetSymbolAddress((void**)&wq1, g_wq1);
    cudaGetSymbolAddress((void**)&wq2, g_wq2);
    __nv_bfloat16 *yt_hi, *yt_lo, *wp_hi, *wp_lo;
    cudaGetSymbolAddress((void**)&yt_hi, g_yt_hi);
    cudaGetSymbolAddress((void**)&yt_lo, g_yt_lo);
    cudaGetSymbolAddress((void**)&wp_hi, g_wp_hi);
    cudaGetSymbolAddress((void**)&wp_lo, g_wp_lo);

    cudaFuncSetAttribute(gemm_mma_kernel,
                         cudaFuncAttributeMaxDynamicSharedMemorySize, 61440);
    cudaFuncSetAttribute(gemm_s8_kernel,
                         cudaFuncAttributeMaxDynamicSharedMemorySize, 61440);

    convert_w_kernel<<<192, 256>>>(qkv_w, proj_w);
    tquant_kernel<<<dim3(128, 8, BB), dim3(32, 8)>>>(x, x1, x2);

    // qkv = W(192x256) . xT + b   (int8 2-level mma)
    gemm_s8_kernel<<<dim3(32, 3, BB), 512, 61440>>>(
        x1, x2, wq1, wq2, qkv_b, qkv, NQKV);

    // fused slide attention -> yt (bf16 split, head-major)
    attn_kernel<<<dim3(16, NHD, BB), 128>>>(qkv, w1, dcb, dc1b, rpb, yt_hi, yt_lo);

    // out = W(256x64) . yT + b   (bf16 3-split mma), A layout: [b][hd][pos][8]
    gemm_mma_kernel<<<dim3(32, 4, BB), 256, 61440>>>(
        yt_hi, yt_lo, wp_hi, wp_lo, proj_b, out, DIMC, CRN,
        (long)CRN * HWSZ, 8L, (long)HWSZ, (long)HWSZ * 8);
}

// round 15
// speedup vs baseline: 1.2633x; 1.2633x over previous
#include <cuda_runtime.h>
#include <cuda_bf16.h>
#include <cstdint>

#define BB    16
#define HWSZ  4096
#define DIMC  256
#define NQKV  192
#define NHD   8
#define CRN   64
#define SCALEF 0.17677669529663687f
#define PLANE 364
#define RSTR  36

typedef unsigned long long ull;
typedef unsigned int u32;

// ---------------- device scratch (allocation-free rule) ----------------
__device__ float g_qkv[BB * NQKV * HWSZ];            // (B,192,4096) fp32
__device__ __nv_bfloat16 g_xt_hi[BB * HWSZ * DIMC];  // (B,4096,256)
__device__ __nv_bfloat16 g_xt_lo[BB * HWSZ * DIMC];
__device__ __nv_bfloat16 g_yt_hi[BB * NHD * HWSZ * 8];  // (B,8,4096,8) head-major
__device__ __nv_bfloat16 g_yt_lo[BB * NHD * HWSZ * 8];
__device__ __nv_bfloat16 g_wq_hi[NQKV * DIMC];
__device__ __nv_bfloat16 g_wq_lo[NQKV * DIMC];
__device__ __nv_bfloat16 g_wp_hi[DIMC * CRN];
__device__ __nv_bfloat16 g_wp_lo[DIMC * CRN];

// ---------------- PTX helpers ----------------
__device__ __forceinline__ ull fma2(ull a, ull b, ull c) {
    ull d; asm("fma.rn.f32x2 %0, %1, %2, %3;" : "=l"(d) : "l"(a), "l"(b), "l"(c)); return d;
}
__device__ __forceinline__ ull add2(ull a, ull b) {
    ull d; asm("add.rn.f32x2 %0, %1, %2;" : "=l"(d) : "l"(a), "l"(b)); return d;
}
__device__ __forceinline__ ull mul2(ull a, ull b) {
    ull d; asm("mul.rn.f32x2 %0, %1, %2;" : "=l"(d) : "l"(a), "l"(b)); return d;
}
__device__ __forceinline__ ull pack2(float lo, float hi) {
    ull d; asm("mov.b64 %0, {%1, %2};" : "=l"(d)
        : "r"(__float_as_uint(lo)), "r"(__float_as_uint(hi))); return d;
}
__device__ __forceinline__ float lo32(ull v) { return __uint_as_float((unsigned)(v & 0xffffffffu)); }
__device__ __forceinline__ float hi32(ull v) { return __uint_as_float((unsigned)(v >> 32)); }

__device__ __forceinline__ void cp16(void* smem, const void* g) {
    unsigned s = (unsigned)__cvta_generic_to_shared(smem);
    asm volatile("cp.async.cg.shared.global [%0], [%1], 16;" :: "r"(s), "l"(g));
}
__device__ __forceinline__ void cp_commit() { asm volatile("cp.async.commit_group;"); }
__device__ __forceinline__ void cp_wait1()  { asm volatile("cp.async.wait_group 1;"); }
__device__ __forceinline__ void cp_wait0()  { asm volatile("cp.async.wait_group 0;"); }

__device__ __forceinline__ u32 smem_u32(const void* p) {
    return (u32)__cvta_generic_to_shared(p);
}
__device__ __forceinline__ void ldsm4(u32* r, u32 addr) {
    asm volatile("ldmatrix.sync.aligned.m8n8.x4.shared.b16 {%0,%1,%2,%3}, [%4];"
        : "=r"(r[0]), "=r"(r[1]), "=r"(r[2]), "=r"(r[3]) : "r"(addr));
}
__device__ __forceinline__ void mma16816(float* c, const u32* a, const u32* b) {
    asm volatile(
        "mma.sync.aligned.m16n8k16.row.col.f32.bf16.bf16.f32 "
        "{%0,%1,%2,%3}, {%4,%5,%6,%7}, {%8,%9}, {%0,%1,%2,%3};"
        : "+f"(c[0]), "+f"(c[1]), "+f"(c[2]), "+f"(c[3])
        : "r"(a[0]), "r"(a[1]), "r"(a[2]), "r"(a[3]), "r"(b[0]), "r"(b[1]));
}
__device__ __forceinline__ unsigned short bf16bits(float v) {
    __nv_bfloat16 h = __float2bfloat16(v);
    return *reinterpret_cast<unsigned short*>(&h);
}

// ---------------- weight bf16 split ----------------
__global__ void convert_w_kernel(const float* __restrict__ qkv_w,
                                 const float* __restrict__ proj_w) {
    int i = blockIdx.x * 256 + threadIdx.x;
    if (i < NQKV * DIMC) {
        float v = qkv_w[i];
        __nv_bfloat16 h = __float2bfloat16(v);
        g_wq_hi[i] = h;
        g_wq_lo[i] = __float2bfloat16(v - __bfloat162float(h));
    }
    if (i < DIMC * CRN) {
        float v = proj_w[i];
        __nv_bfloat16 h = __float2bfloat16(v);
        g_wp_hi[i] = h;
        g_wp_lo[i] = __float2bfloat16(v - __bfloat162float(h));
    }
}

// ---------------- transpose + bf16 split: x [b][256][4096] -> xt [b][4096][256] ----------------
// Tile 32m x 256c, vectorized 8B stores.
__global__ __launch_bounds__(256) void tconv_kernel(const float* __restrict__ src,
                                                    __nv_bfloat16* __restrict__ dhi,
                                                    __nv_bfloat16* __restrict__ dlo) {
    __shared__ float t[DIMC][33];
    const int b  = blockIdx.y;
    const int m0 = blockIdx.x * 32;
    const int tid = threadIdx.x;

    // coalesced load: lanes sweep m for fixed c
    const float* s = src + (long)b * DIMC * HWSZ + m0;
    for (int i = tid; i < DIMC * 32; i += 256) {
        int c = i >> 5, m = i & 31;
        t[c][m] = s[(long)c * HWSZ + m];
    }
    __syncthreads();

    // write: each thread handles 4 consecutive c for one m -> ushort4 stores
    __nv_bfloat16* ph = dhi + ((long)b * HWSZ + m0) * DIMC;
    __nv_bfloat16* pl = dlo + ((long)b * HWSZ + m0) * DIMC;
    for (int i = tid; i < 32 * (DIMC / 4); i += 256) {
        int m = i >> 6, q = (i & 63) * 4;
        ushort4 H, L;
        float v0 = t[q + 0][m], v1 = t[q + 1][m], v2 = t[q + 2][m], v3 = t[q + 3][m];
        H.x = bf16bits(v0); H.y = bf16bits(v1); H.z = bf16bits(v2); H.w = bf16bits(v3);
        __nv_bfloat16 h0 = __float2bfloat16(v0), h1 = __float2bfloat16(v1);
        __nv_bfloat16 h2 = __float2bfloat16(v2), h3 = __float2bfloat16(v3);
        L.x = bf16bits(v0 - __bfloat162float(h0));
        L.y = bf16bits(v1 - __bfloat162float(h1));
        L.z = bf16bits(v2 - __bfloat162float(h2));
        L.w = bf16bits(v3 - __bfloat162float(h3));
        *(ushort4*)&ph[(long)m * DIMC + q] = H;
        *(ushort4*)&pl[(long)m * DIMC + q] = L;
    }
}

// ---------------- bf16-split mma.sync GEMM (qkv): CTA 128m x 64n ----------------
#define STG   30720
#define AROWB 80     // smem row stride bytes (40 bf16)

__global__ __launch_bounds__(256) void gemm_mma_kernel(
    const __nv_bfloat16* __restrict__ aT_hi,
    const __nv_bfloat16* __restrict__ aT_lo,
    const __nv_bfloat16* __restrict__ w_hi,
    const __nv_bfloat16* __restrict__ w_lo,
    const float* __restrict__ bias,
    float* __restrict__ out, int N, int K,
    long aBatch, long aRow, long aK, long aChunk)
{
    extern __shared__ char sm[];
    const int tid  = threadIdx.x;
    const int lane = tid & 31;
    const int warp = tid >> 5;
    const int wm   = warp & 3;
    const int wn   = warp >> 2;
    const int b    = blockIdx.z;
    const int m0   = blockIdx.x * 128;
    const int n0   = blockIdx.y * 64;

    const long abase0 = (long)b * aBatch + (long)m0 * aRow;

    const int a_row  = lane & 15;
    const int a_colB = (lane >> 4) * 16;
    const int b_row  = (lane & 7) + ((lane >> 4) & 1) * 8;
    const int b_colB = ((lane >> 3) & 1) * 16;

    const int aoff = (wm * 32 + a_row) * AROWB + a_colB;
    const int boff = (wn * 32 + b_row) * AROWB + b_colB;

    float acc[2][4][4];
#pragma unroll
    for (int mt = 0; mt < 2; mt++)
#pragma unroll
        for (int ni = 0; ni < 4; ni++)
#pragma unroll
            for (int r = 0; r < 4; r++) acc[mt][ni][r] = 0.f;

    const int KT = K >> 5;

    auto load_stage = [&](int s, int k0) {
        char* Ah = sm + s * STG;
        char* Al = Ah + 10240;
        char* Bh = Ah + 20480;
        char* Bl = Ah + 25600;
        const long abase = abase0 + (long)k0 * aK;
        for (int u = tid; u < 512; u += 256) {
            int r = u >> 2, j = u & 3;
            long go = abase + r * aRow + j * aChunk;
            cp16(Ah + r * AROWB + j * 16, aT_hi + go);
            cp16(Al + r * AROWB + j * 16, aT_lo + go);
        }
        for (int u = tid; u < 256; u += 256) {
            int r = u >> 2, j = u & 3;
            long go = (long)(n0 + r) * K + k0 + j * 8;
            cp16(Bh + r * AROWB + j * 16, w_hi + go);
            cp16(Bl + r * AROWB + j * 16, w_lo + go);
        }
        cp_commit();
    };

    load_stage(0, 0);

    for (int kt = 0; kt < KT; kt++) {
        const int cur = kt & 1;
        const bool more = (kt + 1 < KT);
        if (more) load_stage(cur ^ 1, (kt + 1) * 32);
        if (more) cp_wait1(); else cp_wait0();
        __syncthreads();

        const char* sb = sm + cur * STG;
        const u32 aH = smem_u32(sb) + aoff;
        const u32 aL = aH + 10240;
        const u32 bH = smem_u32(sb) + 20480 + boff;
        const u32 bL = bH + 5120;

#pragma unroll
        for (int kk = 0; kk < 2; kk++) {
            u32 ah[2][4], al[2][4], bh[2][4], bl[2][4];
#pragma unroll
            for (int mt = 0; mt < 2; mt++) {
                ldsm4(ah[mt], aH + mt * 16 * AROWB + kk * 32);
                ldsm4(al[mt], aL + mt * 16 * AROWB + kk * 32);
            }
#pragma unroll
            for (int bt = 0; bt < 2; bt++) {
                ldsm4(bh[bt], bH + bt * 16 * AROWB + kk * 32);
                ldsm4(bl[bt], bL + bt * 16 * AROWB + kk * 32);
            }
#pragma unroll
            for (int mt = 0; mt < 2; mt++)
#pragma unroll
                for (int ni = 0; ni < 4; ni++) {
                    const int bt = ni >> 1, h = (ni & 1) * 2;
                    mma16816(acc[mt][ni], ah[mt], &bh[bt][h]);
                    mma16816(acc[mt][ni], ah[mt], &bl[bt][h]);
                    mma16816(acc[mt][ni], al[mt], &bh[bt][h]);
                }
        }
        __syncthreads();
    }

    float* Cs = (float*)sm;
#pragma unroll
    for (int mt = 0; mt < 2; mt++)
#pragma unroll
        for (int ni = 0; ni < 4; ni++) {
            int mm = wm * 32 + mt * 16 + (lane >> 2);
            int nn = wn * 32 + ni * 8 + (lane & 3) * 2;
            *(float2*)&Cs[mm * 66 + nn]       = make_float2(acc[mt][ni][0], acc[mt][ni][1]);
            *(float2*)&Cs[(mm + 8) * 66 + nn] = make_float2(acc[mt][ni][2], acc[mt][ni][3]);
        }
    __syncthreads();
    for (int u = tid; u < 64 * 128; u += 256) {
        int n = u >> 7, m = u & 127;
        out[((long)b * N + n0 + n) * HWSZ + m0 + m] = Cs[m * 66 + n] + __ldg(&bias[n0 + n]);
    }
}

// ---------------- bf16-split mma.sync GEMM (proj): CTA 64m x 128n ----------------
// Halves A-traffic vs 64n blocks (N=256 -> 2 passes over yt instead of 4).
// Stage layout: Ah 5120 | Al 5120 | Bh 10240 | Bl 10240 = 30720 (same STG).
__global__ __launch_bounds__(256) void gemm_proj_kernel(
    const __nv_bfloat16* __restrict__ aT_hi,
    const __nv_bfloat16* __restrict__ aT_lo,
    const __nv_bfloat16* __restrict__ w_hi,
    const __nv_bfloat16* __restrict__ w_lo,
    const float* __restrict__ bias,
    float* __restrict__ out, int N, int K,
    long aBatch, long aRow, long aK, long aChunk)
{
    extern __shared__ char sm[];
    const int tid  = threadIdx.x;
    const int lane = tid & 31;
    const int warp = tid >> 5;
    const int wm   = warp & 1;    // 2 m-warps
    const int wn   = warp >> 1;   // 4 n-warps
    const int b    = blockIdx.z;
    const int m0   = blockIdx.x * 64;
    const int n0   = blockIdx.y * 128;

    const long abase0 = (long)b * aBatch + (long)m0 * aRow;

    const int a_row  = lane & 15;
    const int a_colB = (lane >> 4) * 16;
    const int b_row  = (lane & 7) + ((lane >> 4) & 1) * 8;
    const int b_colB = ((lane >> 3) & 1) * 16;

    const int aoff = (wm * 32 + a_row) * AROWB + a_colB;
    const int boff = (wn * 32 + b_row) * AROWB + b_colB;

    float acc[2][4][4];
#pragma unroll
    for (int mt = 0; mt < 2; mt++)
#pragma unroll
        for (int ni = 0; ni < 4; ni++)
#pragma unroll
            for (int r = 0; r < 4; r++) acc[mt][ni][r] = 0.f;

    const int KT = K >> 5;   // 2 for K=64

    auto load_stage = [&](int s, int k0) {
        char* Ah = sm + s * STG;
        char* Al = Ah + 5120;
        char* Bh = Ah + 10240;
        char* Bl = Ah + 20480;
        const long abase = abase0 + (long)k0 * aK;
        if (tid < 256) {  // A: 64 rows x 4 chunks
            int r = tid >> 2, j = tid & 3;
            long go = abase + r * aRow + j * aChunk;
            cp16(Ah + r * AROWB + j * 16, aT_hi + go);
            cp16(Al + r * AROWB + j * 16, aT_lo + go);
        }
        for (int u = tid; u < 512; u += 256) {  // B: 128 rows x 4 chunks
            int r = u >> 2, j = u & 3;
            long go = (long)(n0 + r) * K + k0 + j * 8;
            cp16(Bh + r * AROWB + j * 16, w_hi + go);
            cp16(Bl + r * AROWB + j * 16, w_lo + go);
        }
        cp_commit();
    };

    load_stage(0, 0);

    for (int kt = 0; kt < KT; kt++) {
        const int cur = kt & 1;
        const bool more = (kt + 1 < KT);
        if (more) load_stage(cur ^ 1, (kt + 1) * 32);
        if (more) cp_wait1(); else cp_wait0();
        __syncthreads();

        const char* sb = sm + cur * STG;
        const u32 aH = smem_u32(sb) + aoff;
        const u32 aL = aH + 5120;
        const u32 bH = smem_u32(sb) + 10240 + boff;
        const u32 bL = bH + 10240;

#pragma unroll
        for (int kk = 0; kk < 2; kk++) {
            u32 ah[2][4], al[2][4], bh[2][4], bl[2][4];
#pragma unroll
            for (int mt = 0; mt < 2; mt++) {
                ldsm4(ah[mt], aH + mt * 16 * AROWB + kk * 32);
                ldsm4(al[mt], aL + mt * 16 * AROWB + kk * 32);
            }
#pragma unroll
            for (int bt = 0; bt < 2; bt++) {
                ldsm4(bh[bt], bH + bt * 16 * AROWB + kk * 32);
                ldsm4(bl[bt], bL + bt * 16 * AROWB + kk * 32);
            }
#pragma unroll
            for (int mt = 0; mt < 2; mt++)
#pragma unroll
                for (int ni = 0; ni < 4; ni++) {
                    const int bt = ni >> 1, h = (ni & 1) * 2;
                    mma16816(acc[mt][ni], ah[mt], &bh[bt][h]);
                    mma16816(acc[mt][ni], ah[mt], &bl[bt][h]);
                    mma16816(acc[mt][ni], al[mt], &bh[bt][h]);
                }
        }
        __syncthreads();
    }

    // epilogue: Cs [64m][130] (pad 2), coalesced n-major writes
    float* Cs = (float*)sm;
#pragma unroll
    for (int mt = 0; mt < 2; mt++)
#pragma unroll
        for (int ni = 0; ni < 4; ni++) {
            int mm = wm * 32 + mt * 16 + (lane >> 2);
            int nn = wn * 32 + ni * 8 + (lane & 3) * 2;
            *(float2*)&Cs[mm * 130 + nn]       = make_float2(acc[mt][ni][0], acc[mt][ni][1]);
            *(float2*)&Cs[(mm + 8) * 130 + nn] = make_float2(acc[mt][ni][2], acc[mt][ni][3]);
        }
    __syncthreads();
    for (int u = tid; u < 128 * 64; u += 256) {
        int n = u >> 6, m = u & 63;
        out[((long)b * N + n0 + n) * HWSZ + m0 + m] = Cs[m * 130 + n] + __ldg(&bias[n0 + n]);
    }
}

// ---------------- fused slide attention (R12 version, unchanged) ----------------
__global__ __launch_bounds__(128, 3) void attn_kernel(
    const float* __restrict__ qkv,
    const float* __restrict__ w1,
    const float* __restrict__ dcb,
    const float* __restrict__ dc1b,
    const float* __restrict__ rpb,
    __nv_bfloat16* __restrict__ yh,
    __nv_bfloat16* __restrict__ yl)
{
    const int b   = blockIdx.z;
    const int hd  = blockIdx.y;
    const int rt  = blockIdx.x >> 1;
    const int ct  = blockIdx.x & 1;
    const int h0  = rt * 8;
    const int gw0 = ct * 32;

    __shared__ float sk[8 * PLANE];
    __shared__ float sv[8 * PLANE];
    __shared__ ull   sw2[8][81];
    __shared__ ull   sbk2[8][9];
    __shared__ ull   sbv2[8][9];
    __shared__ __nv_bfloat16 syh[256 * 8];
    __shared__ __nv_bfloat16 syl[256 * 8];

    const int tid  = threadIdx.x;
    const int lane = tid & 31;
    const int warp = tid >> 5;
    const int c    = lane & 7;
    const int g    = lane >> 3;

    const float* base = qkv + ((long)b * NQKV + hd * 24) * HWSZ;

    for (int i = tid; i < 648; i += 128) {
        int cc = i / 81, idx = i - cc * 81;
        int t = idx / 9, ii = idx - t * 9;
        float w = w1[cc * 81 + idx] + (t == ii ? 1.f : 0.f);
        sw2[cc][idx] = pack2(w, w);
    }
    for (int i = tid; i < 72; i += 128) {
        int cc = i / 9, t = i - cc * 9;
        float bb = dcb[i] + dc1b[i];
        sbv2[cc][t] = pack2(bb, bb);
        float bk = bb + rpb[hd * 9 + t];
        sbk2[cc][t] = pack2(bk, bk);
    }
    for (int i = tid; i < 8 * 340; i += 128) {
        int cc = i / 340, rem = i - cc * 340;
        int yy = rem / 34, xx = rem - yy * 34;
        int gh = h0 + yy - 1;
        int gx = gw0 + xx - 1;
        float kk = 0.f, vv = 0.f;
        if (gh >= 0 && gh < 64 && gx >= 0 && gx < 64) {
            long off = (long)(8 + cc) * HWSZ + gh * 64 + gx;
            kk = base[off];
            vv = base[off + 8 * HWSZ];
        }
        sk[cc * PLANE + yy * RSTR + xx] = kk;
        sv[cc * PLANE + yy * RSTR + xx] = vv;
    }
    __syncthreads();

    const ull* wrow = sw2[c];

#pragma unroll 1
    for (int step = 0; step < 4; step++) {
        const int task = step * 4 + warp;
        const int row  = task >> 1;
        const int half = task & 1;
        const int w0   = half * 16 + g * 4;
        const int hw   = (h0 + row) * 64 + gw0 + w0;

        float4 qv = *(const float4*)&base[(long)c * HWSZ + hw];
        ull q0 = pack2(qv.x * SCALEF, qv.y * SCALEF);
        ull q1 = pack2(qv.z * SCALEF, qv.w * SCALEF);

        ull nn[3][5];

        {
            const float* p = &sk[c * PLANE + row * RSTR + w0];
#pragma unroll
            for (int ty = 0; ty < 3; ty++) {
                float4 a  = *(const float4*)(p + ty * RSTR);
                float2 a2 = *(const float2*)(p + ty * RSTR + 4);
                nn[ty][0] = pack2(a.x, a.y);
                nn[ty][1] = pack2(a.y, a.z);
                nn[ty][2] = pack2(a.z, a.w);
                nn[ty][3] = pack2(a.w, a2.x);
                nn[ty][4] = pack2(a2.x, a2.y);
            }
        }

        ull lg0[9], lg1[9];
#pragma unroll
        for (int t = 0; t < 9; t++) {
            ull kv0 = sbk2[c][t];
            ull kv1 = kv0;
#pragma unroll
            for (int i = 0; i < 9; i++) {
                const int iy = i / 3, ix = i - iy * 3;
                ull wp = wrow[t * 9 + i];
                kv0 = fma2(wp, nn[iy][ix],     kv0);
                kv1 = fma2(wp, nn[iy][ix + 2], kv1);
            }
            lg0[t] = mul2(q0, kv0);
            lg1[t] = mul2(q1, kv1);
        }

#pragma unroll
        for (int off = 4; off >= 1; off >>= 1)
#pragma unroll
            for (int t = 0; t < 9; t++) {
                lg0[t] = add2(lg0[t], __shfl_xor_sync(0xffffffffu, lg0[t], off));
                lg1[t] = add2(lg1[t], __shfl_xor_sync(0xffffffffu, lg1[t], off));
            }

        ull s0 = 0ULL, s1 = 0ULL;
#pragma unroll
        for (int t = 0; t < 9; t++) {
            lg0[t] = pack2(__expf(lo32(lg0[t])), __expf(hi32(lg0[t])));
            lg1[t] = pack2(__expf(lo32(lg1[t])), __expf(hi32(lg1[t])));
            s0 = add2(s0, lg0[t]);
            s1 = add2(s1, lg1[t]);
        }
        ull inv0 = pack2(__fdividef(1.f, lo32(s0)), __fdividef(1.f, hi32(s0)));
        ull inv1 = pack2(__fdividef(1.f, lo32(s1)), __fdividef(1.f, hi32(s1)));

        {
            const float* p = &sv[c * PLANE + row * RSTR + w0];
#pragma unroll
            for (int ty = 0; ty < 3; ty++) {
                float4 a  = *(const float4*)(p + ty * RSTR);
                float2 a2 = *(const float2*)(p + ty * RSTR + 4);
                nn[ty][0] = pack2(a.x, a.y);
                nn[ty][1] = pack2(a.y, a.z);
                nn[ty][2] = pack2(a.z, a.w);
                nn[ty][3] = pack2(a.w, a2.x);
                nn[ty][4] = pack2(a2.x, a2.y);
            }
        }
        ull o0 = 0ULL, o1 = 0ULL;
#pragma unroll
        for (int t = 0; t < 9; t++) {
            ull vv0 = sbv2[c][t];
            ull vv1 = vv0;
#pragma unroll
            for (int i = 0; i < 9; i++) {
                const int iy = i / 3, ix = i - iy * 3;
                ull wp = wrow[t * 9 + i];
                vv0 = fma2(wp, nn[iy][ix],     vv0);
                vv1 = fma2(wp, nn[iy][ix + 2], vv1);
            }
            o0 = fma2(lg0[t], vv0, o0);
            o1 = fma2(lg1[t], vv1, o1);
        }
        o0 = mul2(o0, inv0);
        o1 = mul2(o1, inv1);

        const int lpos = row * 32 + w0;
        float o[4] = { lo32(o0), hi32(o0), lo32(o1), hi32(o1) };
#pragma unroll
        for (int p = 0; p < 4; p++) {
            __nv_bfloat16 hb = __float2bfloat16(o[p]);
            syh[(lpos + p) * 8 + c] = hb;
            syl[(lpos + p) * 8 + c] = __float2bfloat16(o[p] - __bfloat162float(hb));
        }
    }
    __syncthreads();

    const long ybase0 = ((long)b * NHD + hd) * HWSZ * 8;
    const uint4* sh4 = (const uint4*)syh;
    const uint4* sl4 = (const uint4*)syl;
    for (int i = tid; i < 256; i += 128) {
        int row = i >> 5, j = i & 31;
        long gdst = ybase0 + ((long)(h0 + row) * 64 + gw0) * 8 + j * 8;
        *(uint4*)&yh[gdst] = sh4[i];
        *(uint4*)&yl[gdst] = sl4[i];
    }
}

// ---------------- launch ----------------
extern "C" void kernel_launch(void* const* d_in, const int* in_sizes, int n_in,
                              void* d_out, int out_size) {
    const float* x      = (const float*)d_in[0];
    const float* qkv_w  = (const float*)d_in[5];
    const float* qkv_b  = (const float*)d_in[6];
    const float* dcb    = (const float*)d_in[7];
    const float* w1     = (const float*)d_in[8];
    const float* dc1b   = (const float*)d_in[9];
    const float* rpb    = (const float*)d_in[10];
    const float* proj_w = (const float*)d_in[11];
    const float* proj_b = (const float*)d_in[12];
    float* out = (float*)d_out;

    float* qkv = nullptr;
    cudaGetSymbolAddress((void**)&qkv, g_qkv);
    __nv_bfloat16 *xt_hi, *xt_lo, *yt_hi, *yt_lo, *wq_hi, *wq_lo, *wp_hi, *wp_lo;
    cudaGetSymbolAddress((void**)&xt_hi, g_xt_hi);
    cudaGetSymbolAddress((void**)&xt_lo, g_xt_lo);
    cudaGetSymbolAddress((void**)&yt_hi, g_yt_hi);
    cudaGetSymbolAddress((void**)&yt_lo, g_yt_lo);
    cudaGetSymbolAddress((void**)&wq_hi, g_wq_hi);
    cudaGetSymbolAddress((void**)&wq_lo, g_wq_lo);
    cudaGetSymbolAddress((void**)&wp_hi, g_wp_hi);
    cudaGetSymbolAddress((void**)&wp_lo, g_wp_lo);

    cudaFuncSetAttribute(gemm_mma_kernel,
                         cudaFuncAttributeMaxDynamicSharedMemorySize, 61440);
    cudaFuncSetAttribute(gemm_proj_kernel,
                         cudaFuncAttributeMaxDynamicSharedMemorySize, 61440);

    convert_w_kernel<<<192, 256>>>(qkv_w, proj_w);
    tconv_kernel<<<dim3(128, BB), 256>>>(x, xt_hi, xt_lo);

    // qkv = W(192x256) . xT + b     A layout: [b][pos][256]
    gemm_mma_kernel<<<dim3(32, 3, BB), 256, 61440>>>(
        xt_hi, xt_lo, wq_hi, wq_lo, qkv_b, qkv, NQKV, DIMC,
        (long)HWSZ * DIMC, (long)DIMC, 1L, 8L);

    // fused slide attention -> yt (bf16 split, head-major [b][hd][pos][8])
    attn_kernel<<<dim3(16, NHD, BB), 128>>>(qkv, w1, dcb, dc1b, rpb, yt_hi, yt_lo);

    // out = W(256x64) . yT + b      (CTA 64m x 128n: half the A-traffic)
    gemm_proj_kernel<<<dim3(64, 2, BB), 256, 61440>>>(
        yt_hi, yt_lo, wp_hi, wp_lo, proj_b, out, DIMC, CRN,
        (long)CRN * HWSZ, 8L, (long)HWSZ, (long)HWSZ * 8);
}

// round 16
// speedup vs baseline: 1.3759x; 1.0891x over previous
#include <cuda_runtime.h>
#include <cuda_bf16.h>
#include <cstdint>

#define BB    16
#define HWSZ  4096
#define DIMC  256
#define NQKV  192
#define NHD   8
#define CRN   64
#define SCALEF 0.17677669529663687f
#define PLANE 364
#define RSTR  36

typedef unsigned long long ull;
typedef unsigned int u32;

// ---------------- device scratch (allocation-free rule) ----------------
__device__ float g_qkv[BB * NQKV * HWSZ];            // (B,192,4096) fp32
__device__ __nv_bfloat16 g_xt_hi[BB * HWSZ * DIMC];  // (B,4096,256)
__device__ __nv_bfloat16 g_xt_lo[BB * HWSZ * DIMC];
__device__ __nv_bfloat16 g_yt_hi[BB * NHD * HWSZ * 8];  // (B,8,4096,8) head-major
__device__ __nv_bfloat16 g_yt_lo[BB * NHD * HWSZ * 8];
__device__ __nv_bfloat16 g_wq_hi[NQKV * DIMC];
__device__ __nv_bfloat16 g_wq_lo[NQKV * DIMC];
__device__ __nv_bfloat16 g_wp_hi[DIMC * CRN];
__device__ __nv_bfloat16 g_wp_lo[DIMC * CRN];

// ---------------- PTX helpers ----------------
__device__ __forceinline__ ull fma2(ull a, ull b, ull c) {
    ull d; asm("fma.rn.f32x2 %0, %1, %2, %3;" : "=l"(d) : "l"(a), "l"(b), "l"(c)); return d;
}
__device__ __forceinline__ ull add2(ull a, ull b) {
    ull d; asm("add.rn.f32x2 %0, %1, %2;" : "=l"(d) : "l"(a), "l"(b)); return d;
}
__device__ __forceinline__ ull mul2(ull a, ull b) {
    ull d; asm("mul.rn.f32x2 %0, %1, %2;" : "=l"(d) : "l"(a), "l"(b)); return d;
}
__device__ __forceinline__ ull pack2(float lo, float hi) {
    ull d; asm("mov.b64 %0, {%1, %2};" : "=l"(d)
        : "r"(__float_as_uint(lo)), "r"(__float_as_uint(hi))); return d;
}
__device__ __forceinline__ float lo32(ull v) { return __uint_as_float((unsigned)(v & 0xffffffffu)); }
__device__ __forceinline__ float hi32(ull v) { return __uint_as_float((unsigned)(v >> 32)); }

__device__ __forceinline__ void cp16(void* smem, const void* g) {
    unsigned s = (unsigned)__cvta_generic_to_shared(smem);
    asm volatile("cp.async.cg.shared.global [%0], [%1], 16;" :: "r"(s), "l"(g));
}
__device__ __forceinline__ void cp_commit() { asm volatile("cp.async.commit_group;"); }
__device__ __forceinline__ void cp_wait1()  { asm volatile("cp.async.wait_group 1;"); }
__device__ __forceinline__ void cp_wait0()  { asm volatile("cp.async.wait_group 0;"); }

__device__ __forceinline__ u32 smem_u32(const void* p) {
    return (u32)__cvta_generic_to_shared(p);
}
__device__ __forceinline__ void ldsm4(u32* r, u32 addr) {
    asm volatile("ldmatrix.sync.aligned.m8n8.x4.shared.b16 {%0,%1,%2,%3}, [%4];"
        : "=r"(r[0]), "=r"(r[1]), "=r"(r[2]), "=r"(r[3]) : "r"(addr));
}
__device__ __forceinline__ void mma16816(float* c, const u32* a, const u32* b) {
    asm volatile(
        "mma.sync.aligned.m16n8k16.row.col.f32.bf16.bf16.f32 "
        "{%0,%1,%2,%3}, {%4,%5,%6,%7}, {%8,%9}, {%0,%1,%2,%3};"
        : "+f"(c[0]), "+f"(c[1]), "+f"(c[2]), "+f"(c[3])
        : "r"(a[0]), "r"(a[1]), "r"(a[2]), "r"(a[3]), "r"(b[0]), "r"(b[1]));
}
__device__ __forceinline__ unsigned short bf16bits(float v) {
    __nv_bfloat16 h = __float2bfloat16(v);
    return *reinterpret_cast<unsigned short*>(&h);
}

// ---------------- weight bf16 split ----------------
__global__ void convert_w_kernel(const float* __restrict__ qkv_w,
                                 const float* __restrict__ proj_w) {
    int i = blockIdx.x * 256 + threadIdx.x;
    if (i < NQKV * DIMC) {
        float v = qkv_w[i];
        __nv_bfloat16 h = __float2bfloat16(v);
        g_wq_hi[i] = h;
        g_wq_lo[i] = __float2bfloat16(v - __bfloat162float(h));
    }
    if (i < DIMC * CRN) {
        float v = proj_w[i];
        __nv_bfloat16 h = __float2bfloat16(v);
        g_wp_hi[i] = h;
        g_wp_lo[i] = __float2bfloat16(v - __bfloat162float(h));
    }
}

// ---------------- transpose + bf16 split: x [b][256][4096] -> xt [b][4096][256] ----------------
__global__ __launch_bounds__(256) void tconv_kernel(const float* __restrict__ src,
                                                    __nv_bfloat16* __restrict__ dhi,
                                                    __nv_bfloat16* __restrict__ dlo) {
    __shared__ float t[DIMC][33];
    const int b  = blockIdx.y;
    const int m0 = blockIdx.x * 32;
    const int tid = threadIdx.x;

    const float* s = src + (long)b * DIMC * HWSZ + m0;
    for (int i = tid; i < DIMC * 32; i += 256) {
        int c = i >> 5, m = i & 31;
        t[c][m] = s[(long)c * HWSZ + m];
    }
    __syncthreads();

    __nv_bfloat16* ph = dhi + ((long)b * HWSZ + m0) * DIMC;
    __nv_bfloat16* pl = dlo + ((long)b * HWSZ + m0) * DIMC;
    for (int i = tid; i < 32 * (DIMC / 4); i += 256) {
        int m = i >> 6, q = (i & 63) * 4;
        ushort4 H, L;
        float v0 = t[q + 0][m], v1 = t[q + 1][m], v2 = t[q + 2][m], v3 = t[q + 3][m];
        H.x = bf16bits(v0); H.y = bf16bits(v1); H.z = bf16bits(v2); H.w = bf16bits(v3);
        __nv_bfloat16 h0 = __float2bfloat16(v0), h1 = __float2bfloat16(v1);
        __nv_bfloat16 h2 = __float2bfloat16(v2), h3 = __float2bfloat16(v3);
        L.x = bf16bits(v0 - __bfloat162float(h0));
        L.y = bf16bits(v1 - __bfloat162float(h1));
        L.z = bf16bits(v2 - __bfloat162float(h2));
        L.w = bf16bits(v3 - __bfloat162float(h3));
        *(ushort4*)&ph[(long)m * DIMC + q] = H;
        *(ushort4*)&pl[(long)m * DIMC + q] = L;
    }
}

// ---------------- bf16-split mma.sync GEMM (qkv): CTA 128m x 64n ----------------
#define STG   30720
#define AROWB 80

__global__ __launch_bounds__(256) void gemm_mma_kernel(
    const __nv_bfloat16* __restrict__ aT_hi,
    const __nv_bfloat16* __restrict__ aT_lo,
    const __nv_bfloat16* __restrict__ w_hi,
    const __nv_bfloat16* __restrict__ w_lo,
    const float* __restrict__ bias,
    float* __restrict__ out, int N, int K,
    long aBatch, long aRow, long aK, long aChunk)
{
    extern __shared__ char sm[];
    const int tid  = threadIdx.x;
    const int lane = tid & 31;
    const int warp = tid >> 5;
    const int wm   = warp & 3;
    const int wn   = warp >> 2;
    const int b    = blockIdx.z;
    const int m0   = blockIdx.x * 128;
    const int n0   = blockIdx.y * 64;

    const long abase0 = (long)b * aBatch + (long)m0 * aRow;

    const int a_row  = lane & 15;
    const int a_colB = (lane >> 4) * 16;
    const int b_row  = (lane & 7) + ((lane >> 4) & 1) * 8;
    const int b_colB = ((lane >> 3) & 1) * 16;

    const int aoff = (wm * 32 + a_row) * AROWB + a_colB;
    const int boff = (wn * 32 + b_row) * AROWB + b_colB;

    float acc[2][4][4];
#pragma unroll
    for (int mt = 0; mt < 2; mt++)
#pragma unroll
        for (int ni = 0; ni < 4; ni++)
#pragma unroll
            for (int r = 0; r < 4; r++) acc[mt][ni][r] = 0.f;

    const int KT = K >> 5;

    auto load_stage = [&](int s, int k0) {
        char* Ah = sm + s * STG;
        char* Al = Ah + 10240;
        char* Bh = Ah + 20480;
        char* Bl = Ah + 25600;
        const long abase = abase0 + (long)k0 * aK;
        for (int u = tid; u < 512; u += 256) {
            int r = u >> 2, j = u & 3;
            long go = abase + r * aRow + j * aChunk;
            cp16(Ah + r * AROWB + j * 16, aT_hi + go);
            cp16(Al + r * AROWB + j * 16, aT_lo + go);
        }
        for (int u = tid; u < 256; u += 256) {
            int r = u >> 2, j = u & 3;
            long go = (long)(n0 + r) * K + k0 + j * 8;
            cp16(Bh + r * AROWB + j * 16, w_hi + go);
            cp16(Bl + r * AROWB + j * 16, w_lo + go);
        }
        cp_commit();
    };

    load_stage(0, 0);

    for (int kt = 0; kt < KT; kt++) {
        const int cur = kt & 1;
        const bool more = (kt + 1 < KT);
        if (more) load_stage(cur ^ 1, (kt + 1) * 32);
        if (more) cp_wait1(); else cp_wait0();
        __syncthreads();

        const char* sb = sm + cur * STG;
        const u32 aH = smem_u32(sb) + aoff;
        const u32 aL = aH + 10240;
        const u32 bH = smem_u32(sb) + 20480 + boff;
        const u32 bL = bH + 5120;

#pragma unroll
        for (int kk = 0; kk < 2; kk++) {
            u32 ah[2][4], al[2][4], bh[2][4], bl[2][4];
#pragma unroll
            for (int mt = 0; mt < 2; mt++) {
                ldsm4(ah[mt], aH + mt * 16 * AROWB + kk * 32);
                ldsm4(al[mt], aL + mt * 16 * AROWB + kk * 32);
            }
#pragma unroll
            for (int bt = 0; bt < 2; bt++) {
                ldsm4(bh[bt], bH + bt * 16 * AROWB + kk * 32);
                ldsm4(bl[bt], bL + bt * 16 * AROWB + kk * 32);
            }
#pragma unroll
            for (int mt = 0; mt < 2; mt++)
#pragma unroll
                for (int ni = 0; ni < 4; ni++) {
                    const int bt = ni >> 1, h = (ni & 1) * 2;
                    mma16816(acc[mt][ni], ah[mt], &bh[bt][h]);
                    mma16816(acc[mt][ni], ah[mt], &bl[bt][h]);
                    mma16816(acc[mt][ni], al[mt], &bh[bt][h]);
                }
        }
        __syncthreads();
    }

    float* Cs = (float*)sm;
#pragma unroll
    for (int mt = 0; mt < 2; mt++)
#pragma unroll
        for (int ni = 0; ni < 4; ni++) {
            int mm = wm * 32 + mt * 16 + (lane >> 2);
            int nn = wn * 32 + ni * 8 + (lane & 3) * 2;
            *(float2*)&Cs[mm * 66 + nn]       = make_float2(acc[mt][ni][0], acc[mt][ni][1]);
            *(float2*)&Cs[(mm + 8) * 66 + nn] = make_float2(acc[mt][ni][2], acc[mt][ni][3]);
        }
    __syncthreads();
    for (int u = tid; u < 64 * 128; u += 256) {
        int n = u >> 7, m = u & 127;
        out[((long)b * N + n0 + n) * HWSZ + m0 + m] = Cs[m * 66 + n] + __ldg(&bias[n0 + n]);
    }
}

// ---------------- bf16-split mma.sync GEMM (proj): CTA 64m x 128n ----------------
__global__ __launch_bounds__(256) void gemm_proj_kernel(
    const __nv_bfloat16* __restrict__ aT_hi,
    const __nv_bfloat16* __restrict__ aT_lo,
    const __nv_bfloat16* __restrict__ w_hi,
    const __nv_bfloat16* __restrict__ w_lo,
    const float* __restrict__ bias,
    float* __restrict__ out, int N, int K,
    long aBatch, long aRow, long aK, long aChunk)
{
    extern __shared__ char sm[];
    const int tid  = threadIdx.x;
    const int lane = tid & 31;
    const int warp = tid >> 5;
    const int wm   = warp & 1;
    const int wn   = warp >> 1;
    const int b    = blockIdx.z;
    const int m0   = blockIdx.x * 64;
    const int n0   = blockIdx.y * 128;

    const long abase0 = (long)b * aBatch + (long)m0 * aRow;

    const int a_row  = lane & 15;
    const int a_colB = (lane >> 4) * 16;
    const int b_row  = (lane & 7) + ((lane >> 4) & 1) * 8;
    const int b_colB = ((lane >> 3) & 1) * 16;

    const int aoff = (wm * 32 + a_row) * AROWB + a_colB;
    const int boff = (wn * 32 + b_row) * AROWB + b_colB;

    float acc[2][4][4];
#pragma unroll
    for (int mt = 0; mt < 2; mt++)
#pragma unroll
        for (int ni = 0; ni < 4; ni++)
#pragma unroll
            for (int r = 0; r < 4; r++) acc[mt][ni][r] = 0.f;

    const int KT = K >> 5;

    auto load_stage = [&](int s, int k0) {
        char* Ah = sm + s * STG;
        char* Al = Ah + 5120;
        char* Bh = Ah + 10240;
        char* Bl = Ah + 20480;
        const long abase = abase0 + (long)k0 * aK;
        if (tid < 256) {
            int r = tid >> 2, j = tid & 3;
            long go = abase + r * aRow + j * aChunk;
            cp16(Ah + r * AROWB + j * 16, aT_hi + go);
            cp16(Al + r * AROWB + j * 16, aT_lo + go);
        }
        for (int u = tid; u < 512; u += 256) {
            int r = u >> 2, j = u & 3;
            long go = (long)(n0 + r) * K + k0 + j * 8;
            cp16(Bh + r * AROWB + j * 16, w_hi + go);
            cp16(Bl + r * AROWB + j * 16, w_lo + go);
        }
        cp_commit();
    };

    load_stage(0, 0);

    for (int kt = 0; kt < KT; kt++) {
        const int cur = kt & 1;
        const bool more = (kt + 1 < KT);
        if (more) load_stage(cur ^ 1, (kt + 1) * 32);
        if (more) cp_wait1(); else cp_wait0();
        __syncthreads();

        const char* sb = sm + cur * STG;
        const u32 aH = smem_u32(sb) + aoff;
        const u32 aL = aH + 5120;
        const u32 bH = smem_u32(sb) + 10240 + boff;
        const u32 bL = bH + 10240;

#pragma unroll
        for (int kk = 0; kk < 2; kk++) {
            u32 ah[2][4], al[2][4], bh[2][4], bl[2][4];
#pragma unroll
            for (int mt = 0; mt < 2; mt++) {
                ldsm4(ah[mt], aH + mt * 16 * AROWB + kk * 32);
                ldsm4(al[mt], aL + mt * 16 * AROWB + kk * 32);
            }
#pragma unroll
            for (int bt = 0; bt < 2; bt++) {
                ldsm4(bh[bt], bH + bt * 16 * AROWB + kk * 32);
                ldsm4(bl[bt], bL + bt * 16 * AROWB + kk * 32);
            }
#pragma unroll
            for (int mt = 0; mt < 2; mt++)
#pragma unroll
                for (int ni = 0; ni < 4; ni++) {
                    const int bt = ni >> 1, h = (ni & 1) * 2;
                    mma16816(acc[mt][ni], ah[mt], &bh[bt][h]);
                    mma16816(acc[mt][ni], ah[mt], &bl[bt][h]);
                    mma16816(acc[mt][ni], al[mt], &bh[bt][h]);
                }
        }
        __syncthreads();
    }

    float* Cs = (float*)sm;
#pragma unroll
    for (int mt = 0; mt < 2; mt++)
#pragma unroll
        for (int ni = 0; ni < 4; ni++) {
            int mm = wm * 32 + mt * 16 + (lane >> 2);
            int nn = wn * 32 + ni * 8 + (lane & 3) * 2;
            *(float2*)&Cs[mm * 130 + nn]       = make_float2(acc[mt][ni][0], acc[mt][ni][1]);
            *(float2*)&Cs[(mm + 8) * 130 + nn] = make_float2(acc[mt][ni][2], acc[mt][ni][3]);
        }
    __syncthreads();
    for (int u = tid; u < 128 * 64; u += 256) {
        int n = u >> 6, m = u & 63;
        out[((long)b * N + n0 + n) * HWSZ + m0 + m] = Cs[m * 130 + n] + __ldg(&bias[n0 + n]);
    }
}

// ---------------- fused slide attention (proven version, unchanged) ----------------
__global__ __launch_bounds__(128, 3) void attn_kernel(
    const float* __restrict__ qkv,
    const float* __restrict__ w1,
    const float* __restrict__ dcb,
    const float* __restrict__ dc1b,
    const float* __restrict__ rpb,
    __nv_bfloat16* __restrict__ yh,
    __nv_bfloat16* __restrict__ yl)
{
    const int b   = blockIdx.z;
    const int hd  = blockIdx.y;
    const int rt  = blockIdx.x >> 1;
    const int ct  = blockIdx.x & 1;
    const int h0  = rt * 8;
    const int gw0 = ct * 32;

    __shared__ float sk[8 * PLANE];
    __shared__ float sv[8 * PLANE];
    __shared__ ull   sw2[8][81];
    __shared__ ull   sbk2[8][9];
    __shared__ ull   sbv2[8][9];
    __shared__ __nv_bfloat16 syh[256 * 8];
    __shared__ __nv_bfloat16 syl[256 * 8];

    const int tid  = threadIdx.x;
    const int lane = tid & 31;
    const int warp = tid >> 5;
    const int c    = lane & 7;
    const int g    = lane >> 3;

    const float* base = qkv + ((long)b * NQKV + hd * 24) * HWSZ;

    for (int i = tid; i < 648; i += 128) {
        int cc = i / 81, idx = i - cc * 81;
        int t = idx / 9, ii = idx - t * 9;
        float w = w1[cc * 81 + idx] + (t == ii ? 1.f : 0.f);
        sw2[cc][idx] = pack2(w, w);
    }
    for (int i = tid; i < 72; i += 128) {
        int cc = i / 9, t = i - cc * 9;
        float bb = dcb[i] + dc1b[i];
        sbv2[cc][t] = pack2(bb, bb);
        float bk = bb + rpb[hd * 9 + t];
        sbk2[cc][t] = pack2(bk, bk);
    }
    for (int i = tid; i < 8 * 340; i += 128) {
        int cc = i / 340, rem = i - cc * 340;
        int yy = rem / 34, xx = rem - yy * 34;
        int gh = h0 + yy - 1;
        int gx = gw0 + xx - 1;
        float kk = 0.f, vv = 0.f;
        if (gh >= 0 && gh < 64 && gx >= 0 && gx < 64) {
            long off = (long)(8 + cc) * HWSZ + gh * 64 + gx;
            kk = base[off];
            vv = base[off + 8 * HWSZ];
        }
        sk[cc * PLANE + yy * RSTR + xx] = kk;
        sv[cc * PLANE + yy * RSTR + xx] = vv;
    }
    __syncthreads();

    const ull* wrow = sw2[c];

#pragma unroll 1
    for (int step = 0; step < 4; step++) {
        const int task = step * 4 + warp;
        const int row  = task >> 1;
        const int half = task & 1;
        const int w0   = half * 16 + g * 4;
        const int hw   = (h0 + row) * 64 + gw0 + w0;

        float4 qv = *(const float4*)&base[(long)c * HWSZ + hw];
        ull q0 = pack2(qv.x * SCALEF, qv.y * SCALEF);
        ull q1 = pack2(qv.z * SCALEF, qv.w * SCALEF);

        ull nn[3][5];

        {
            const float* p = &sk[c * PLANE + row * RSTR + w0];
#pragma unroll
            for (int ty = 0; ty < 3; ty++) {
                float4 a  = *(const float4*)(p + ty * RSTR);
                float2 a2 = *(const float2*)(p + ty * RSTR + 4);
                nn[ty][0] = pack2(a.x, a.y);
                nn[ty][1] = pack2(a.y, a.z);
                nn[ty][2] = pack2(a.z, a.w);
                nn[ty][3] = pack2(a.w, a2.x);
                nn[ty][4] = pack2(a2.x, a2.y);
            }
        }

        ull lg0[9], lg1[9];
#pragma unroll
        for (int t = 0; t < 9; t++) {
            ull kv0 = sbk2[c][t];
            ull kv1 = kv0;
#pragma unroll
            for (int i = 0; i < 9; i++) {
                const int iy = i / 3, ix = i - iy * 3;
                ull wp = wrow[t * 9 + i];
                kv0 = fma2(wp, nn[iy][ix],     kv0);
                kv1 = fma2(wp, nn[iy][ix + 2], kv1);
            }
            lg0[t] = mul2(q0, kv0);
            lg1[t] = mul2(q1, kv1);
        }

#pragma unroll
        for (int off = 4; off >= 1; off >>= 1)
#pragma unroll
            for (int t = 0; t < 9; t++) {
                lg0[t] = add2(lg0[t], __shfl_xor_sync(0xffffffffu, lg0[t], off));
                lg1[t] = add2(lg1[t], __shfl_xor_sync(0xffffffffu, lg1[t], off));
            }

        ull s0 = 0ULL, s1 = 0ULL;
#pragma unroll
        for (int t = 0; t < 9; t++) {
            lg0[t] = pack2(__expf(lo32(lg0[t])), __expf(hi32(lg0[t])));
            lg1[t] = pack2(__expf(lo32(lg1[t])), __expf(hi32(lg1[t])));
            s0 = add2(s0, lg0[t]);
            s1 = add2(s1, lg1[t]);
        }
        ull inv0 = pack2(__fdividef(1.f, lo32(s0)), __fdividef(1.f, hi32(s0)));
        ull inv1 = pack2(__fdividef(1.f, lo32(s1)), __fdividef(1.f, hi32(s1)));

        {
            const float* p = &sv[c * PLANE + row * RSTR + w0];
#pragma unroll
            for (int ty = 0; ty < 3; ty++) {
                float4 a  = *(const float4*)(p + ty * RSTR);
                float2 a2 = *(const float2*)(p + ty * RSTR + 4);
                nn[ty][0] = pack2(a.x, a.y);
                nn[ty][1] = pack2(a.y, a.z);
                nn[ty][2] = pack2(a.z, a.w);
                nn[ty][3] = pack2(a.w, a2.x);
                nn[ty][4] = pack2(a2.x, a2.y);
            }
        }
        ull o0 = 0ULL, o1 = 0ULL;
#pragma unroll
        for (int t = 0; t < 9; t++) {
            ull vv0 = sbv2[c][t];
            ull vv1 = vv0;
#pragma unroll
            for (int i = 0; i < 9; i++) {
                const int iy = i / 3, ix = i - iy * 3;
                ull wp = wrow[t * 9 + i];
                vv0 = fma2(wp, nn[iy][ix],     vv0);
                vv1 = fma2(wp, nn[iy][ix + 2], vv1);
            }
            o0 = fma2(lg0[t], vv0, o0);
            o1 = fma2(lg1[t], vv1, o1);
        }
        o0 = mul2(o0, inv0);
        o1 = mul2(o1, inv1);

        const int lpos = row * 32 + w0;
        float o[4] = { lo32(o0), hi32(o0), lo32(o1), hi32(o1) };
#pragma unroll
        for (int p = 0; p < 4; p++) {
            __nv_bfloat16 hb = __float2bfloat16(o[p]);
            syh[(lpos + p) * 8 + c] = hb;
            syl[(lpos + p) * 8 + c] = __float2bfloat16(o[p] - __bfloat162float(hb));
        }
    }
    __syncthreads();

    const long ybase0 = ((long)b * NHD + hd) * HWSZ * 8;
    const uint4* sh4 = (const uint4*)syh;
    const uint4* sl4 = (const uint4*)syl;
    for (int i = tid; i < 256; i += 128) {
        int row = i >> 5, j = i & 31;
        long gdst = ybase0 + ((long)(h0 + row) * 64 + gw0) * 8 + j * 8;
        *(uint4*)&yh[gdst] = sh4[i];
        *(uint4*)&yl[gdst] = sl4[i];
    }
}

// ---------------- launch: two-stream batch-split pipeline ----------------
extern "C" void kernel_launch(void* const* d_in, const int* in_sizes, int n_in,
                              void* d_out, int out_size) {
    const float* x      = (const float*)d_in[0];
    const float* qkv_w  = (const float*)d_in[5];
    const float* qkv_b  = (const float*)d_in[6];
    const float* dcb    = (const float*)d_in[7];
    const float* w1     = (const float*)d_in[8];
    const float* dc1b   = (const float*)d_in[9];
    const float* rpb    = (const float*)d_in[10];
    const float* proj_w = (const float*)d_in[11];
    const float* proj_b = (const float*)d_in[12];
    float* out = (float*)d_out;

    float* qkv = nullptr;
    cudaGetSymbolAddress((void**)&qkv, g_qkv);
    __nv_bfloat16 *xt_hi, *xt_lo, *yt_hi, *yt_lo, *wq_hi, *wq_lo, *wp_hi, *wp_lo;
    cudaGetSymbolAddress((void**)&xt_hi, g_xt_hi);
    cudaGetSymbolAddress((void**)&xt_lo, g_xt_lo);
    cudaGetSymbolAddress((void**)&yt_hi, g_yt_hi);
    cudaGetSymbolAddress((void**)&yt_lo, g_yt_lo);
    cudaGetSymbolAddress((void**)&wq_hi, g_wq_hi);
    cudaGetSymbolAddress((void**)&wq_lo, g_wq_lo);
    cudaGetSymbolAddress((void**)&wp_hi, g_wp_hi);
    cudaGetSymbolAddress((void**)&wp_lo, g_wp_lo);

    static cudaStream_t s2 = nullptr;
    static cudaEvent_t evF = nullptr, evW = nullptr, evJ = nullptr;
    if (s2 == nullptr) {
        cudaStreamCreateWithFlags(&s2, cudaStreamNonBlocking);
        cudaEventCreateWithFlags(&evF, cudaEventDisableTiming);
        cudaEventCreateWithFlags(&evW, cudaEventDisableTiming);
        cudaEventCreateWithFlags(&evJ, cudaEventDisableTiming);
        cudaFuncSetAttribute(gemm_mma_kernel,
                             cudaFuncAttributeMaxDynamicSharedMemorySize, 61440);
        cudaFuncSetAttribute(gemm_proj_kernel,
                             cudaFuncAttributeMaxDynamicSharedMemorySize, 61440);
    }

    const int HB = BB / 2;
    // half-2 pointer offsets
    const float* x2            = x      + (long)HB * DIMC * HWSZ;
    __nv_bfloat16* xt_hi2      = xt_hi  + (long)HB * HWSZ * DIMC;
    __nv_bfloat16* xt_lo2      = xt_lo  + (long)HB * HWSZ * DIMC;
    float* qkv2                = qkv    + (long)HB * NQKV * HWSZ;
    __nv_bfloat16* yt_hi2      = yt_hi  + (long)HB * NHD * HWSZ * 8;
    __nv_bfloat16* yt_lo2      = yt_lo  + (long)HB * NHD * HWSZ * 8;
    float* out2                = out    + (long)HB * DIMC * HWSZ;

    // fork: s2 joins capture after this event
    cudaEventRecord(evF, 0);
    cudaStreamWaitEvent(s2, evF, 0);

    // ---- stream 0: weights + half 1 ----
    convert_w_kernel<<<192, 256>>>(qkv_w, proj_w);
    cudaEventRecord(evW, 0);   // weights ready (for s2's qkv/proj)

    tconv_kernel<<<dim3(128, HB), 256>>>(x, xt_hi, xt_lo);
    gemm_mma_kernel<<<dim3(32, 3, HB), 256, 61440>>>(
        xt_hi, xt_lo, wq_hi, wq_lo, qkv_b, qkv, NQKV, DIMC,
        (long)HWSZ * DIMC, (long)DIMC, 1L, 8L);
    attn_kernel<<<dim3(16, NHD, HB), 128>>>(qkv, w1, dcb, dc1b, rpb, yt_hi, yt_lo);
    gemm_proj_kernel<<<dim3(64, 2, HB), 256, 61440>>>(
        yt_hi, yt_lo, wp_hi, wp_lo, proj_b, out, DIMC, CRN,
        (long)CRN * HWSZ, 8L, (long)HWSZ, (long)HWSZ * 8);

    // ---- stream s2: half 2 ----
    tconv_kernel<<<dim3(128, HB), 256, 0, s2>>>(x2, xt_hi2, xt_lo2);
    cudaStreamWaitEvent(s2, evW, 0);
    gemm_mma_kernel<<<dim3(32, 3, HB), 256, 61440, s2>>>(
        xt_hi2, xt_lo2, wq_hi, wq_lo, qkv_b, qkv2, NQKV, DIMC,
        (long)HWSZ * DIMC, (long)DIMC, 1L, 8L);
    attn_kernel<<<dim3(16, NHD, HB), 128, 0, s2>>>(qkv2, w1, dcb, dc1b, rpb, yt_hi2, yt_lo2);
    gemm_proj_kernel<<<dim3(64, 2, HB), 256, 61440, s2>>>(
        yt_hi2, yt_lo2, wp_hi, wp_lo, proj_b, out2, DIMC, CRN,
        (long)CRN * HWSZ, 8L, (long)HWSZ, (long)HWSZ * 8);

    // join
    cudaEventRecord(evJ, s2);
    cudaStreamWaitEvent(0, evJ, 0);
}